// round 5
// baseline (speedup 1.0000x reference)
#include <cuda_runtime.h>
#include <math.h>

#define N_ 128
#define H_ 256
#define B_ 16

// -------- device scratch --------
__device__ float g_P[H_*H_];          // W1^T W1
__device__ float g_Q[H_*H_];          // W2 W2^T
__device__ float g_W2T[N_*H_];        // W2T[i*H+h] = W2[h*N+i]
__device__ float g_s[B_*H_];
__device__ float g_c[B_*H_];
__device__ float g_Avec[B_*N_];
__device__ float g_Cvec[B_*N_];
__device__ float g_vn[B_];
__device__ float g_A2[2*B_*H_*H_];    // split-K partial A2: [ka][b][g][h]
__device__ float g_part[B_*32];       // nrm^2/2 partials

// -------- kernel 0: P = W1^T W1, Q = W2 W2^T, W2T --------
__global__ void k_prep(const float* __restrict__ W1, const float* __restrict__ W2){
    int z = blockIdx.z;
    int tid = threadIdx.x;
    if (z == 2){
        __shared__ float ts[32][33];
        int tb = blockIdx.y*4 + blockIdx.x;
        int i0 = (tb & 3) * 32;
        int r = tid >> 5, c = tid & 31;
        for (int rep = 0; rep < 2; rep++){
            int h0 = ((tb >> 2) + rep*4) * 32;
            #pragma unroll
            for (int rr = r; rr < 32; rr += 8)
                ts[c][rr] = W2[(h0+rr)*N_ + i0 + c];
            __syncthreads();
            #pragma unroll
            for (int rr = r; rr < 32; rr += 8)
                g_W2T[(i0+rr)*H_ + h0 + c] = ts[rr][c];
            __syncthreads();
        }
        return;
    }
    __shared__ float As[16][65];
    __shared__ float Bs[16][65];
    int g0 = blockIdx.y*64, h0 = blockIdx.x*64;
    int ty = tid>>4, tx = tid&15;
    float acc[4][4];
    #pragma unroll
    for (int i = 0; i < 4; i++)
        #pragma unroll
        for (int j = 0; j < 4; j++) acc[i][j] = 0.f;

    for (int a0 = 0; a0 < N_; a0 += 16){
        if (z == 0){
            #pragma unroll
            for (int it = 0; it < 4; it++){
                int l = tid + it*256; int a = l>>6, gg = l&63;
                As[a][gg] = W1[(a0+a)*H_ + g0+gg];
                Bs[a][gg] = W1[(a0+a)*H_ + h0+gg];
            }
        } else {
            #pragma unroll
            for (int it = 0; it < 4; it++){
                int l = tid + it*256; int gg = l>>4, k = l&15;
                As[k][gg] = W2[(g0+gg)*N_ + a0+k];
                Bs[k][gg] = W2[(h0+gg)*N_ + a0+k];
            }
        }
        __syncthreads();
        #pragma unroll
        for (int a = 0; a < 16; a++){
            float ra[4], rb[4];
            #pragma unroll
            for (int i = 0; i < 4; i++) ra[i] = As[a][ty*4+i];
            #pragma unroll
            for (int j = 0; j < 4; j++) rb[j] = Bs[a][tx*4+j];
            #pragma unroll
            for (int i = 0; i < 4; i++)
                #pragma unroll
                for (int j = 0; j < 4; j++) acc[i][j] += ra[i]*rb[j];
        }
        __syncthreads();
    }
    float* dst = (z == 0) ? g_P : g_Q;
    #pragma unroll
    for (int i = 0; i < 4; i++)
        #pragma unroll
        for (int j = 0; j < 4; j++)
            dst[(g0+ty*4+i)*H_ + h0 + tx*4+j] = acc[i][j];
}

// -------- kernel 1: per-sample vectors (1024 threads, 4 per output) --------
__global__ void k_vectors(const float* __restrict__ tptr,
                          const float* __restrict__ state,
                          const float* __restrict__ x0,
                          const float* __restrict__ x1,
                          const float* __restrict__ W1,
                          const float* __restrict__ b1){
    int b = blockIdx.x, tid = threadIdx.x;
    __shared__ float xs[N_], vs[N_], red[N_];
    __shared__ float swv[H_], cwy[H_], pvs[H_], cwz[H_];

    float tval = *tptr;
    float window = 4.f * tval * (1.f - tval);
    if (tid < N_){
        float dev = state[b*N_ + tid];
        float v   = state[(B_+b)*N_ + tid];
        float x0v = x0[b*N_ + tid];
        xs[tid] = x0v + tval*(x1[b*N_ + tid] - x0v) + window*dev;
        vs[tid] = v;
        red[tid] = v*v;
    }
    __syncthreads();

    if (tid < 32){
        float a0 = red[tid] + red[tid+32] + red[tid+64] + red[tid+96];
        #pragma unroll
        for (int o = 16; o; o >>= 1) a0 += __shfl_xor_sync(0xffffffffu, a0, o);
        if (tid == 0) g_vn[b] = sqrtf(a0);
    }

    int h = tid >> 2, q = tid & 3;
    {
        int k0 = q*32;
        float u = 0.f, y = 0.f, w = 0.f;
        #pragma unroll 8
        for (int j = 0; j < 32; j++){
            int k = k0 + j;
            float xv = xs[k], vv = vs[k];
            float w1 = W1[k*H_ + h];
            u += xv*w1;
            y += vv*w1;
            w += g_W2T[k*H_ + h]*vv;
        }
        u += __shfl_xor_sync(0xffffffffu, u, 1); u += __shfl_xor_sync(0xffffffffu, u, 2);
        y += __shfl_xor_sync(0xffffffffu, y, 1); y += __shfl_xor_sync(0xffffffffu, y, 2);
        w += __shfl_xor_sync(0xffffffffu, w, 1); w += __shfl_xor_sync(0xffffffffu, w, 2);
        float th = tanhf(u + b1[h]);
        float s = 1.f - th*th;
        float c = -2.f*th*s;
        if (q == 0){
            g_s[b*H_ + h] = s;
            g_c[b*H_ + h] = c;
            swv[h] = s*w;
            cwy[h] = c*w*y;
        }
        __syncthreads();

        int a0 = q*64;
        float z = 0.f, q2 = 0.f;
        #pragma unroll 8
        for (int j = 0; j < 64; j++){
            int a = a0 + j;
            float pa = g_P[a*H_ + h];
            z  += pa*swv[a];
            q2 += pa*cwy[a];
        }
        z  += __shfl_xor_sync(0xffffffffu, z, 1);  z  += __shfl_xor_sync(0xffffffffu, z, 2);
        q2 += __shfl_xor_sync(0xffffffffu, q2, 1); q2 += __shfl_xor_sync(0xffffffffu, q2, 2);
        if (q == 0){
            pvs[h] = c*y*z + s*q2;
            cwz[h] = c*w*z;
        }
    }
    __syncthreads();

    if (tid < 4*N_){
        int i = tid >> 2, qq = tid & 3;
        int h0 = qq*64;
        float A = 0.f, C = 0.f;
        #pragma unroll 8
        for (int j = 0; j < 64; j++){
            int hh = h0 + j;
            A += g_W2T[i*H_ + hh]*pvs[hh];
            C += W1[i*H_ + hh]*cwz[hh];
        }
        A += __shfl_xor_sync(0xffffffffu, A, 1); A += __shfl_xor_sync(0xffffffffu, A, 2);
        C += __shfl_xor_sync(0xffffffffu, C, 1); C += __shfl_xor_sync(0xffffffffu, C, 2);
        if (qq == 0){
            g_Avec[b*N_ + i] = A;
            g_Cvec[b*N_ + i] = 2.f*C;
        }
    }
}

// -------- kernel 2: A2 partial = P[:, ka-half] diag(s) Q[ka-half, :]  --------
// grid (4, 4, 2B): z = b*2 + ka; 512 blocks.
__global__ void k_A2(){
    int zz = blockIdx.z;
    int b = zz >> 1, ka = zz & 1;
    int g0 = blockIdx.y*64, h0 = blockIdx.x*64;
    int tid = threadIdx.x;
    int ty = tid>>4, tx = tid&15;
    __shared__ float Ps[16][65];
    __shared__ float Qs[16][65];
    float acc[4][4];
    #pragma unroll
    for (int i = 0; i < 4; i++)
        #pragma unroll
        for (int j = 0; j < 4; j++) acc[i][j] = 0.f;

    const float* sb = g_s + b*H_;
    int abase = ka*128;
    for (int a0 = abase; a0 < abase + 128; a0 += 16){
        #pragma unroll
        for (int it = 0; it < 4; it++){
            int l = tid + it*256; int a = l>>6, gg = l&63;
            Ps[a][gg] = g_P[(a0+a)*H_ + g0 + gg];           // P symmetric
            Qs[a][gg] = g_Q[(a0+a)*H_ + h0 + gg] * sb[a0+a];
        }
        __syncthreads();
        #pragma unroll
        for (int a = 0; a < 16; a++){
            float ra[4], rb[4];
            #pragma unroll
            for (int i = 0; i < 4; i++) ra[i] = Ps[a][ty*4+i];
            #pragma unroll
            for (int j = 0; j < 4; j++) rb[j] = Qs[a][tx*4+j];
            #pragma unroll
            for (int i = 0; i < 4; i++)
                #pragma unroll
                for (int j = 0; j < 4; j++) acc[i][j] += ra[i]*rb[j];
        }
        __syncthreads();
    }
    float* dst = g_A2 + (ka*B_ + b)*H_*H_;
    #pragma unroll
    for (int i = 0; i < 4; i++)
        #pragma unroll
        for (int j = 0; j < 4; j++)
            dst[(g0+ty*4+i)*H_ + h0 + tx*4+j] = acc[i][j];
}

// -------- kernel 3: split-K fused A1 = A2 S P + weighted reduction --------
// grid (4, 4, 2B): z = b*2 + ka; 512 blocks.
// Term = sum_gh c_g c_h P_gh ( Q_gh A1_gh + A2_gh A2_hg );  nrm^2 = 2*Term.
// A1 is linear in K-half partials; the A2*A2T elementwise term goes to ka==0 only.
__global__ void k_nrm(){
    int zz = blockIdx.z;
    int b = zz >> 1, ka = zz & 1;
    int g0 = blockIdx.y*64, h0 = blockIdx.x*64;
    int tid = threadIdx.x;
    int ty = tid>>4, tx = tid&15;
    __shared__ float As[16][65];
    __shared__ float Bs[16][65];
    float acc[4][4];
    #pragma unroll
    for (int i = 0; i < 4; i++)
        #pragma unroll
        for (int j = 0; j < 4; j++) acc[i][j] = 0.f;

    const float* A2lo = g_A2 + b*H_*H_;          // ka=0 partial
    const float* A2hi = g_A2 + (B_ + b)*H_*H_;   // ka=1 partial
    const float* sb   = g_s + b*H_;
    int abase = ka*128;
    for (int a0 = abase; a0 < abase + 128; a0 += 16){
        #pragma unroll
        for (int it = 0; it < 4; it++){
            int l = tid + it*256;
            {   int gg = l>>4, a = l&15;
                int idx = (g0+gg)*H_ + a0 + a;
                As[a][gg] = (A2lo[idx] + A2hi[idx]) * sb[a0+a]; }
            {   int a = l>>6, hh = l&63;
                Bs[a][hh] = g_P[(a0+a)*H_ + h0 + hh]; }
        }
        __syncthreads();
        #pragma unroll
        for (int a = 0; a < 16; a++){
            float ra[4], rb[4];
            #pragma unroll
            for (int i = 0; i < 4; i++) ra[i] = As[a][ty*4+i];
            #pragma unroll
            for (int j = 0; j < 4; j++) rb[j] = Bs[a][tx*4+j];
            #pragma unroll
            for (int i = 0; i < 4; i++)
                #pragma unroll
                for (int j = 0; j < 4; j++) acc[i][j] += ra[i]*rb[j];
        }
        __syncthreads();
    }

    const float* cb = g_c + b*H_;
    float local = 0.f;
    #pragma unroll
    for (int i = 0; i < 4; i++){
        int g = g0 + ty*4 + i;
        float cg = cb[g];
        #pragma unroll
        for (int j = 0; j < 4; j++){
            int h = h0 + tx*4 + j;
            float w  = cg*cb[h]*g_P[g*H_ + h];
            local += w * g_Q[g*H_ + h] * acc[i][j];
            if (ka == 0){
                float a2  = A2lo[g*H_ + h] + A2hi[g*H_ + h];
                float a2t = A2lo[h*H_ + g] + A2hi[h*H_ + g];
                local += w * a2 * a2t;
            }
        }
    }
    __shared__ float red[256];
    red[tid] = local;
    __syncthreads();
    for (int st = 128; st > 0; st >>= 1){
        if (tid < st) red[tid] += red[tid + st];
        __syncthreads();
    }
    if (tid == 0)
        g_part[b*32 + blockIdx.y*8 + blockIdx.x*2 + ka] = red[0];
}

// -------- kernel 4: finalize --------
__global__ void k_final(const float* __restrict__ state, float* __restrict__ out){
    int b = blockIdx.x, tid = threadIdx.x;   // 128 threads
    __shared__ float nrm_s;
    if (tid == 0){
        float sum = 0.f;
        #pragma unroll
        for (int i = 0; i < 32; i++) sum += g_part[b*32 + i];
        nrm_s = sqrtf(fmaxf(2.f*sum, 0.f));   // nrm^2 = 2 * Sigma
    }
    __syncthreads();
    float nrm = nrm_s;
    float vn  = g_vn[b];
    float v   = state[(B_+b)*N_ + tid];
    float dev = state[b*N_ + tid];
    float a = -(g_Avec[b*N_ + tid] - 0.5f*g_Cvec[b*N_ + tid])
              / ((nrm + 1e-6f) * (vn + 1e-6f));
    out[b*N_ + tid]       = v;
    out[(B_+b)*N_ + tid]  = a - 0.1f*dev;
}

// -------- launch --------
extern "C" void kernel_launch(void* const* d_in, const int* in_sizes, int n_in,
                              void* d_out, int out_size){
    const float* t     = (const float*)d_in[0];
    const float* state = (const float*)d_in[1];
    const float* x0    = (const float*)d_in[2];
    const float* x1    = (const float*)d_in[3];
    const float* W1    = (const float*)d_in[4];
    const float* b1    = (const float*)d_in[5];
    const float* W2    = (const float*)d_in[6];
    float* out = (float*)d_out;

    k_prep   <<<dim3(4,4,3),     256>>>(W1, W2);
    k_vectors<<<B_,              1024>>>(t, state, x0, x1, W1, b1);
    k_A2     <<<dim3(4,4,2*B_),  256>>>();
    k_nrm    <<<dim3(4,4,2*B_),  256>>>();
    k_final  <<<B_,              N_>>>(state, out);
}

// round 6
// speedup vs baseline: 1.1398x; 1.1398x over previous
#include <cuda_runtime.h>
#include <math.h>

#define N_ 128
#define H_ 256
#define B_ 16

// -------- device scratch --------
__device__ float g_P[H_*H_];        // W1^T W1
__device__ float g_Q[H_*H_];        // W2 W2^T
__device__ float g_W2T[N_*H_];      // W2T[i*H+h] = W2[h*N+i]
__device__ float g_s[B_*H_];
__device__ float g_c[B_*H_];
__device__ float g_Avec[B_*N_];
__device__ float g_Cvec[B_*N_];
__device__ float g_vn[B_];
__device__ float g_A2[B_*H_*H_];    // A2 = P S Q per sample
__device__ float g_part[B_*16];     // nrm^2/2 tile partials

// -------- kernel 0: P = W1^T W1, Q = W2 W2^T, W2T --------
__global__ void k_prep(const float* __restrict__ W1, const float* __restrict__ W2){
    int z = blockIdx.z;
    int tid = threadIdx.x;
    if (z == 2){
        __shared__ float ts[32][33];
        int tb = blockIdx.y*4 + blockIdx.x;
        int i0 = (tb & 3) * 32;
        int r = tid >> 5, c = tid & 31;
        for (int rep = 0; rep < 2; rep++){
            int h0 = ((tb >> 2) + rep*4) * 32;
            #pragma unroll
            for (int rr = r; rr < 32; rr += 8)
                ts[c][rr] = W2[(h0+rr)*N_ + i0 + c];
            __syncthreads();
            #pragma unroll
            for (int rr = r; rr < 32; rr += 8)
                g_W2T[(i0+rr)*H_ + h0 + c] = ts[rr][c];
            __syncthreads();
        }
        return;
    }
    __shared__ float As[16][65];
    __shared__ float Bs[16][65];
    int g0 = blockIdx.y*64, h0 = blockIdx.x*64;
    int ty = tid>>4, tx = tid&15;
    float acc[4][4];
    #pragma unroll
    for (int i = 0; i < 4; i++)
        #pragma unroll
        for (int j = 0; j < 4; j++) acc[i][j] = 0.f;

    for (int a0 = 0; a0 < N_; a0 += 16){
        if (z == 0){
            #pragma unroll
            for (int it = 0; it < 4; it++){
                int l = tid + it*256; int a = l>>6, gg = l&63;
                As[a][gg] = W1[(a0+a)*H_ + g0+gg];
                Bs[a][gg] = W1[(a0+a)*H_ + h0+gg];
            }
        } else {
            #pragma unroll
            for (int it = 0; it < 4; it++){
                int l = tid + it*256; int gg = l>>4, k = l&15;
                As[k][gg] = W2[(g0+gg)*N_ + a0+k];
                Bs[k][gg] = W2[(h0+gg)*N_ + a0+k];
            }
        }
        __syncthreads();
        #pragma unroll
        for (int a = 0; a < 16; a++){
            float ra[4], rb[4];
            #pragma unroll
            for (int i = 0; i < 4; i++) ra[i] = As[a][ty*4+i];
            #pragma unroll
            for (int j = 0; j < 4; j++) rb[j] = Bs[a][tx*4+j];
            #pragma unroll
            for (int i = 0; i < 4; i++)
                #pragma unroll
                for (int j = 0; j < 4; j++) acc[i][j] += ra[i]*rb[j];
        }
        __syncthreads();
    }
    float* dst = (z == 0) ? g_P : g_Q;
    #pragma unroll
    for (int i = 0; i < 4; i++)
        #pragma unroll
        for (int j = 0; j < 4; j++)
            dst[(g0+ty*4+i)*H_ + h0 + tx*4+j] = acc[i][j];
}

// -------- kernel 1: per-sample vectors (1024 threads, 4 per output) --------
__global__ void k_vectors(const float* __restrict__ tptr,
                          const float* __restrict__ state,
                          const float* __restrict__ x0,
                          const float* __restrict__ x1,
                          const float* __restrict__ W1,
                          const float* __restrict__ b1){
    int b = blockIdx.x, tid = threadIdx.x;
    __shared__ float xs[N_], vs[N_], red[N_];
    __shared__ float swv[H_], cwy[H_], pvs[H_], cwz[H_];

    float tval = *tptr;
    float window = 4.f * tval * (1.f - tval);
    if (tid < N_){
        float dev = state[b*N_ + tid];
        float v   = state[(B_+b)*N_ + tid];
        float x0v = x0[b*N_ + tid];
        xs[tid] = x0v + tval*(x1[b*N_ + tid] - x0v) + window*dev;
        vs[tid] = v;
        red[tid] = v*v;
    }
    __syncthreads();

    if (tid < 32){
        float a0 = red[tid] + red[tid+32] + red[tid+64] + red[tid+96];
        #pragma unroll
        for (int o = 16; o; o >>= 1) a0 += __shfl_xor_sync(0xffffffffu, a0, o);
        if (tid == 0) g_vn[b] = sqrtf(a0);
    }

    int h = tid >> 2, q = tid & 3;
    {
        int k0 = q*32;
        float u = 0.f, y = 0.f, w = 0.f;
        #pragma unroll 8
        for (int j = 0; j < 32; j++){
            int k = k0 + j;
            float xv = xs[k], vv = vs[k];
            float w1 = W1[k*H_ + h];
            u += xv*w1;
            y += vv*w1;
            w += g_W2T[k*H_ + h]*vv;
        }
        u += __shfl_xor_sync(0xffffffffu, u, 1); u += __shfl_xor_sync(0xffffffffu, u, 2);
        y += __shfl_xor_sync(0xffffffffu, y, 1); y += __shfl_xor_sync(0xffffffffu, y, 2);
        w += __shfl_xor_sync(0xffffffffu, w, 1); w += __shfl_xor_sync(0xffffffffu, w, 2);
        float th = tanhf(u + b1[h]);
        float s = 1.f - th*th;
        float c = -2.f*th*s;
        if (q == 0){
            g_s[b*H_ + h] = s;
            g_c[b*H_ + h] = c;
            swv[h] = s*w;
            cwy[h] = c*w*y;
        }
        __syncthreads();

        int a0 = q*64;
        float z = 0.f, q2 = 0.f;
        #pragma unroll 8
        for (int j = 0; j < 64; j++){
            int a = a0 + j;
            float pa = g_P[a*H_ + h];
            z  += pa*swv[a];
            q2 += pa*cwy[a];
        }
        z  += __shfl_xor_sync(0xffffffffu, z, 1);  z  += __shfl_xor_sync(0xffffffffu, z, 2);
        q2 += __shfl_xor_sync(0xffffffffu, q2, 1); q2 += __shfl_xor_sync(0xffffffffu, q2, 2);
        if (q == 0){
            pvs[h] = c*y*z + s*q2;
            cwz[h] = c*w*z;
        }
    }
    __syncthreads();

    if (tid < 4*N_){
        int i = tid >> 2, qq = tid & 3;
        int h0 = qq*64;
        float A = 0.f, C = 0.f;
        #pragma unroll 8
        for (int j = 0; j < 64; j++){
            int hh = h0 + j;
            A += g_W2T[i*H_ + hh]*pvs[hh];
            C += W1[i*H_ + hh]*cwz[hh];
        }
        A += __shfl_xor_sync(0xffffffffu, A, 1); A += __shfl_xor_sync(0xffffffffu, A, 2);
        C += __shfl_xor_sync(0xffffffffu, C, 1); C += __shfl_xor_sync(0xffffffffu, C, 2);
        if (qq == 0){
            g_Avec[b*N_ + i] = A;
            g_Cvec[b*N_ + i] = 2.f*C;
        }
    }
}

// -------- kernel 2: A2[b] = P diag(s_b) Q  (64x64 tile, 128 thr, 8x4 micro) --------
__global__ void __launch_bounds__(128) k_A2(){
    int b  = blockIdx.z;
    int g0 = blockIdx.y*64, h0 = blockIdx.x*64;
    int tid = threadIdx.x;
    int ty = tid >> 4, tx = tid & 15;       // ty 0..7, tx 0..15
    __shared__ float Ps[16][68];            // 272B rows: 16B-aligned
    __shared__ float Qs[16][68];
    __shared__ float ssm[H_];
    ssm[tid] = g_s[b*H_ + tid];
    ssm[tid+128] = g_s[b*H_ + tid + 128];

    float acc[8][4];
    #pragma unroll
    for (int i = 0; i < 8; i++)
        #pragma unroll
        for (int j = 0; j < 4; j++) acc[i][j] = 0.f;
    __syncthreads();

    for (int a0 = 0; a0 < H_; a0 += 16){
        #pragma unroll
        for (int it = 0; it < 8; it++){
            int l = tid + it*128; int a = l>>6, gg = l&63;
            Ps[a][gg] = g_P[(a0+a)*H_ + g0 + gg];           // P symmetric
            Qs[a][gg] = g_Q[(a0+a)*H_ + h0 + gg] * ssm[a0+a];
        }
        __syncthreads();
        #pragma unroll
        for (int a = 0; a < 16; a++){
            float ra[8], rb[4];
            *(float4*)&ra[0] = *(const float4*)&Ps[a][ty*8];
            *(float4*)&ra[4] = *(const float4*)&Ps[a][ty*8+4];
            *(float4*)&rb[0] = *(const float4*)&Qs[a][tx*4];
            #pragma unroll
            for (int i = 0; i < 8; i++)
                #pragma unroll
                for (int j = 0; j < 4; j++) acc[i][j] += ra[i]*rb[j];
        }
        __syncthreads();
    }
    float* dst = g_A2 + b*H_*H_;
    #pragma unroll
    for (int i = 0; i < 8; i++){
        int g = g0 + ty*8 + i;
        *(float4*)&dst[g*H_ + h0 + tx*4] = *(float4*)&acc[i][0];
    }
}

// -------- kernel 3: fused A1 = A2 diag(s) P + weighted reduction --------
// partial = sum_{g,h in tile} c_g c_h P_gh (Q_gh A1_gh + A2_gh A2_hg)
__global__ void __launch_bounds__(128) k_nrm(){
    int b  = blockIdx.z;
    int g0 = blockIdx.y*64, h0 = blockIdx.x*64;
    int tid = threadIdx.x;
    int ty = tid >> 4, tx = tid & 15;
    __shared__ float As[16][68];
    __shared__ float Bs[16][68];
    __shared__ float ssm[H_];
    ssm[tid] = g_s[b*H_ + tid];
    ssm[tid+128] = g_s[b*H_ + tid + 128];

    float acc[8][4];
    #pragma unroll
    for (int i = 0; i < 8; i++)
        #pragma unroll
        for (int j = 0; j < 4; j++) acc[i][j] = 0.f;
    __syncthreads();

    const float* A2b = g_A2 + b*H_*H_;
    for (int a0 = 0; a0 < H_; a0 += 16){
        #pragma unroll
        for (int it = 0; it < 8; it++){
            int l = tid + it*128;
            {   int gg = l>>4, a = l&15;    // contiguous 64B global reads
                As[a][gg] = A2b[(g0+gg)*H_ + a0 + a] * ssm[a0+a]; }
        }
        #pragma unroll
        for (int it = 0; it < 8; it++){
            int l = tid + it*128; int a = l>>6, hh = l&63;
            Bs[a][hh] = g_P[(a0+a)*H_ + h0 + hh];
        }
        __syncthreads();
        #pragma unroll
        for (int a = 0; a < 16; a++){
            float ra[8], rb[4];
            *(float4*)&ra[0] = *(const float4*)&As[a][ty*8];
            *(float4*)&ra[4] = *(const float4*)&As[a][ty*8+4];
            *(float4*)&rb[0] = *(const float4*)&Bs[a][tx*4];
            #pragma unroll
            for (int i = 0; i < 8; i++)
                #pragma unroll
                for (int j = 0; j < 4; j++) acc[i][j] += ra[i]*rb[j];
        }
        __syncthreads();
    }

    const float* cb = g_c + b*H_;
    float local = 0.f;
    #pragma unroll
    for (int i = 0; i < 8; i++){
        int g = g0 + ty*8 + i;
        float cg = cb[g];
        #pragma unroll
        for (int j = 0; j < 4; j++){
            int h = h0 + tx*4 + j;
            float pg  = g_P[g*H_ + h];
            float qg  = g_Q[g*H_ + h];
            float a2  = A2b[g*H_ + h];
            float a2t = A2b[h*H_ + g];
            local += cg*cb[h]*pg*(qg*acc[i][j] + a2*a2t);
        }
    }
    __shared__ float red[128];
    red[tid] = local;
    __syncthreads();
    for (int st = 64; st > 0; st >>= 1){
        if (tid < st) red[tid] += red[tid + st];
        __syncthreads();
    }
    if (tid == 0) g_part[b*16 + blockIdx.y*4 + blockIdx.x] = red[0];
}

// -------- kernel 4: finalize --------
__global__ void k_final(const float* __restrict__ state, float* __restrict__ out){
    int b = blockIdx.x, tid = threadIdx.x;   // 128 threads
    __shared__ float nrm_s;
    if (tid == 0){
        float sum = 0.f;
        #pragma unroll
        for (int i = 0; i < 16; i++) sum += g_part[b*16 + i];
        nrm_s = sqrtf(fmaxf(2.f*sum, 0.f));
    }
    __syncthreads();
    float nrm = nrm_s;
    float vn  = g_vn[b];
    float v   = state[(B_+b)*N_ + tid];
    float dev = state[b*N_ + tid];
    float a = -(g_Avec[b*N_ + tid] - 0.5f*g_Cvec[b*N_ + tid])
              / ((nrm + 1e-6f) * (vn + 1e-6f));
    out[b*N_ + tid]       = v;
    out[(B_+b)*N_ + tid]  = a - 0.1f*dev;
}

// -------- launch --------
extern "C" void kernel_launch(void* const* d_in, const int* in_sizes, int n_in,
                              void* d_out, int out_size){
    const float* t     = (const float*)d_in[0];
    const float* state = (const float*)d_in[1];
    const float* x0    = (const float*)d_in[2];
    const float* x1    = (const float*)d_in[3];
    const float* W1    = (const float*)d_in[4];
    const float* b1    = (const float*)d_in[5];
    const float* W2    = (const float*)d_in[6];
    float* out = (float*)d_out;

    k_prep   <<<dim3(4,4,3),  256>>>(W1, W2);
    k_vectors<<<B_,           1024>>>(t, state, x0, x1, W1, b1);
    k_A2     <<<dim3(4,4,B_), 128>>>();
    k_nrm    <<<dim3(4,4,B_), 128>>>();
    k_final  <<<B_,           N_>>>(state, out);
}

// round 7
// speedup vs baseline: 1.8832x; 1.6522x over previous
#include <cuda_runtime.h>
#include <math.h>

#define N_ 128
#define H_ 256
#define B_ 16

// -------- device scratch --------
__device__ float g_P[H_*H_];        // W1^T W1
__device__ float g_Q[H_*H_];        // W2 W2^T
__device__ float g_s[B_*H_];
__device__ float g_c[B_*H_];
__device__ float g_Avec[B_*N_];
__device__ float g_Cvec[B_*N_];
__device__ float g_vn[B_];
__device__ float g_A2[B_*H_*H_];    // A2 = P S Q per sample
__device__ float g_part[B_*16];     // nrm^2/2 tile partials

// ==================== stage 1: fused prep + vectors ====================
// blocks 0..15: P tiles, 16..31: Q tiles, 32..47: per-sample vectors.
__global__ void __launch_bounds__(256) k_stage1(
        const float* __restrict__ W1, const float* __restrict__ W2,
        const float* __restrict__ tptr, const float* __restrict__ state,
        const float* __restrict__ x0,  const float* __restrict__ x1,
        const float* __restrict__ b1){
    int bid = blockIdx.x;
    int tid = threadIdx.x;

    if (bid < 32){
        // ---- P = W1^T W1 (z=0) or Q = W2 W2^T (z=1), 64x64 tile ----
        int z = bid >> 4, tile = bid & 15;
        int g0 = (tile >> 2)*64, h0 = (tile & 3)*64;
        __shared__ float As[16][68];
        __shared__ float Bs[16][68];
        int ty = tid >> 4, tx = tid & 15;
        float acc[4][4];
        #pragma unroll
        for (int i = 0; i < 4; i++)
            #pragma unroll
            for (int j = 0; j < 4; j++) acc[i][j] = 0.f;

        for (int a0 = 0; a0 < N_; a0 += 16){
            if (z == 0){
                int a = tid >> 4, q4 = (tid & 15)*4;
                float4 av = *(const float4*)&W1[(a0+a)*H_ + g0 + q4];
                float4 bv = *(const float4*)&W1[(a0+a)*H_ + h0 + q4];
                *(float4*)&As[a][q4] = av;
                *(float4*)&Bs[a][q4] = bv;
            } else {
                int gg = tid >> 2, kq = (tid & 3)*4;
                float4 av = *(const float4*)&W2[(g0+gg)*N_ + a0 + kq];
                float4 bv = *(const float4*)&W2[(h0+gg)*N_ + a0 + kq];
                As[kq+0][gg] = av.x; As[kq+1][gg] = av.y;
                As[kq+2][gg] = av.z; As[kq+3][gg] = av.w;
                Bs[kq+0][gg] = bv.x; Bs[kq+1][gg] = bv.y;
                Bs[kq+2][gg] = bv.z; Bs[kq+3][gg] = bv.w;
            }
            __syncthreads();
            #pragma unroll
            for (int a = 0; a < 16; a++){
                float4 ra = *(const float4*)&As[a][ty*4];
                float4 rb = *(const float4*)&Bs[a][tx*4];
                float rav[4] = {ra.x, ra.y, ra.z, ra.w};
                float rbv[4] = {rb.x, rb.y, rb.z, rb.w};
                #pragma unroll
                for (int i = 0; i < 4; i++)
                    #pragma unroll
                    for (int j = 0; j < 4; j++) acc[i][j] += rav[i]*rbv[j];
            }
            __syncthreads();
        }
        float* dst = (z == 0) ? g_P : g_Q;
        #pragma unroll
        for (int i = 0; i < 4; i++){
            float4 o = make_float4(acc[i][0], acc[i][1], acc[i][2], acc[i][3]);
            *(float4*)&dst[(g0+ty*4+i)*H_ + h0 + tx*4] = o;
        }
        return;
    }

    // ---- per-sample vector pipeline (z = P x done as W1^T(W1 x)) ----
    int b = bid - 32;
    __shared__ float xs[N_], vs[N_], red[N_];
    __shared__ float ws[H_], swv[H_], cwy[H_], pvs[H_], cwz[H_];
    __shared__ float r1[N_], r2[N_], Ap[2*N_];

    float tval = *tptr;
    float window = 4.f * tval * (1.f - tval);
    if (tid < N_){
        float dev = state[b*N_ + tid];
        float v   = state[(B_+b)*N_ + tid];
        float x0v = x0[b*N_ + tid];
        xs[tid] = x0v + tval*(x1[b*N_ + tid] - x0v) + window*dev;
        vs[tid] = v;
        red[tid] = v*v;
    }
    __syncthreads();

    if (tid < 32){
        float a0 = red[tid] + red[tid+32] + red[tid+64] + red[tid+96];
        #pragma unroll
        for (int o = 16; o; o >>= 1) a0 += __shfl_xor_sync(0xffffffffu, a0, o);
        if (tid == 0) g_vn[b] = sqrtf(a0);
    }

    int h = tid;
    int wid = tid >> 5, lane = tid & 31;

    // u_h = x.W1[:,h], y_h = v.W1[:,h]   (coalesced across h)
    float u = 0.f, y = 0.f;
    #pragma unroll 8
    for (int k = 0; k < N_; k++){
        float w1 = W1[k*H_ + h];
        u += xs[k]*w1;
        y += vs[k]*w1;
    }
    // w_h = W2[h,:] . v  via warp-per-row (coalesced lanes)
    for (int r = 0; r < 32; r++){
        int row = wid*32 + r;
        const float* wr = W2 + row*N_;
        float sum = wr[lane]*vs[lane] + wr[lane+32]*vs[lane+32]
                  + wr[lane+64]*vs[lane+64] + wr[lane+96]*vs[lane+96];
        #pragma unroll
        for (int o = 16; o; o >>= 1) sum += __shfl_xor_sync(0xffffffffu, sum, o);
        if (lane == 0) ws[row] = sum;
    }
    __syncthreads();

    float th = tanhf(u + b1[h]);
    float s = 1.f - th*th;
    float c = -2.f*th*s;
    g_s[b*H_ + h] = s;
    g_c[b*H_ + h] = c;
    float wv = ws[h];
    swv[h] = s*wv;
    cwy[h] = c*wv*y;
    __syncthreads();

    // r1 = W1*swv, r2 = W1*cwy  (warp-per-row, 16 rows/warp)
    for (int r = 0; r < 16; r++){
        int row = wid*16 + r;
        const float* wr = W1 + row*H_;
        float s1 = 0.f, s2 = 0.f;
        #pragma unroll
        for (int jj = 0; jj < 8; jj++){
            int hh = lane + jj*32;
            float w1 = wr[hh];
            s1 += w1*swv[hh];
            s2 += w1*cwy[hh];
        }
        #pragma unroll
        for (int o = 16; o; o >>= 1){
            s1 += __shfl_xor_sync(0xffffffffu, s1, o);
            s2 += __shfl_xor_sync(0xffffffffu, s2, o);
        }
        if (lane == 0){ r1[row] = s1; r2[row] = s2; }
    }
    __syncthreads();

    // z_h = W1[:,h].r1, q2_h = W1[:,h].r2  (coalesced)
    float z = 0.f, q2 = 0.f;
    #pragma unroll 8
    for (int k = 0; k < N_; k++){
        float w1 = W1[k*H_ + h];
        z  += w1*r1[k];
        q2 += w1*r2[k];
    }
    pvs[h] = c*y*z + s*q2;
    cwz[h] = c*wv*z;
    __syncthreads();

    // A_i = sum_h W2[h,i] pv_h  (two half-sums, coalesced across i)
    {
        int i = tid & 127, q = tid >> 7;
        float A = 0.f;
        #pragma unroll 8
        for (int j = 0; j < 128; j++){
            int hh = q*128 + j;
            A += W2[hh*N_ + i]*pvs[hh];
        }
        Ap[tid] = A;
    }
    // C_i = sum_h W1[i,h] cwz_h  (warp-per-row)
    for (int r = 0; r < 16; r++){
        int row = wid*16 + r;
        const float* wr = W1 + row*H_;
        float sC = 0.f;
        #pragma unroll
        for (int jj = 0; jj < 8; jj++){
            int hh = lane + jj*32;
            sC += wr[hh]*cwz[hh];
        }
        #pragma unroll
        for (int o = 16; o; o >>= 1) sC += __shfl_xor_sync(0xffffffffu, sC, o);
        if (lane == 0) g_Cvec[b*N_ + row] = 2.f*sC;
    }
    __syncthreads();
    if (tid < N_) g_Avec[b*N_ + tid] = Ap[tid] + Ap[tid + N_];
}

// ==================== stage 2: A2[b] = P diag(s) Q ====================
__global__ void __launch_bounds__(256) k_A2(){
    int b  = blockIdx.z;
    int g0 = blockIdx.y*64, h0 = blockIdx.x*64;
    int tid = threadIdx.x;
    int ty = tid >> 4, tx = tid & 15;
    __shared__ float Ps[16][68];
    __shared__ float Qs[16][68];
    __shared__ float ssm[H_];
    ssm[tid] = g_s[b*H_ + tid];
    float acc[4][4];
    #pragma unroll
    for (int i = 0; i < 4; i++)
        #pragma unroll
        for (int j = 0; j < 4; j++) acc[i][j] = 0.f;
    __syncthreads();

    int a = tid >> 4, q4 = (tid & 15)*4;
    for (int a0 = 0; a0 < H_; a0 += 16){
        float4 pv = *(const float4*)&g_P[(a0+a)*H_ + g0 + q4];   // P symmetric
        float4 qv = *(const float4*)&g_Q[(a0+a)*H_ + h0 + q4];
        float sa = ssm[a0+a];
        qv.x *= sa; qv.y *= sa; qv.z *= sa; qv.w *= sa;
        *(float4*)&Ps[a][q4] = pv;
        *(float4*)&Qs[a][q4] = qv;
        __syncthreads();
        #pragma unroll
        for (int k = 0; k < 16; k++){
            float4 ra = *(const float4*)&Ps[k][ty*4];
            float4 rb = *(const float4*)&Qs[k][tx*4];
            float rav[4] = {ra.x, ra.y, ra.z, ra.w};
            float rbv[4] = {rb.x, rb.y, rb.z, rb.w};
            #pragma unroll
            for (int i = 0; i < 4; i++)
                #pragma unroll
                for (int j = 0; j < 4; j++) acc[i][j] += rav[i]*rbv[j];
        }
        __syncthreads();
    }
    float* dst = g_A2 + b*H_*H_;
    #pragma unroll
    for (int i = 0; i < 4; i++){
        float4 o = make_float4(acc[i][0], acc[i][1], acc[i][2], acc[i][3]);
        *(float4*)&dst[(g0+ty*4+i)*H_ + h0 + tx*4] = o;
    }
}

// ========== stage 3: fused A1 = A2 diag(s) P + weighted reduction ==========
// partial = sum_{g,h in tile} c_g c_h P_gh (Q_gh A1_gh + A2_gh A2_hg)
__global__ void __launch_bounds__(256) k_nrm(){
    int b  = blockIdx.z;
    int g0 = blockIdx.y*64, h0 = blockIdx.x*64;
    int tid = threadIdx.x;
    int ty = tid >> 4, tx = tid & 15;
    __shared__ float As[16][68];
    __shared__ float Bs[16][68];
    __shared__ float ssm[H_];
    ssm[tid] = g_s[b*H_ + tid];
    float acc[4][4];
    #pragma unroll
    for (int i = 0; i < 4; i++)
        #pragma unroll
        for (int j = 0; j < 4; j++) acc[i][j] = 0.f;
    __syncthreads();

    const float* A2b = g_A2 + b*H_*H_;
    int gg = tid >> 2, aq = (tid & 3)*4;         // for As stage
    int ab = tid >> 4, q4 = (tid & 15)*4;        // for Bs stage
    for (int a0 = 0; a0 < H_; a0 += 16){
        float4 av = *(const float4*)&A2b[(g0+gg)*H_ + a0 + aq];
        As[aq+0][gg] = av.x*ssm[a0+aq+0];
        As[aq+1][gg] = av.y*ssm[a0+aq+1];
        As[aq+2][gg] = av.z*ssm[a0+aq+2];
        As[aq+3][gg] = av.w*ssm[a0+aq+3];
        float4 bv = *(const float4*)&g_P[(a0+ab)*H_ + h0 + q4];
        *(float4*)&Bs[ab][q4] = bv;
        __syncthreads();
        #pragma unroll
        for (int k = 0; k < 16; k++){
            float4 ra = *(const float4*)&As[k][ty*4];
            float4 rb = *(const float4*)&Bs[k][tx*4];
            float rav[4] = {ra.x, ra.y, ra.z, ra.w};
            float rbv[4] = {rb.x, rb.y, rb.z, rb.w};
            #pragma unroll
            for (int i = 0; i < 4; i++)
                #pragma unroll
                for (int j = 0; j < 4; j++) acc[i][j] += rav[i]*rbv[j];
        }
        __syncthreads();
    }

    const float* cb = g_c + b*H_;
    float local = 0.f;
    #pragma unroll
    for (int i = 0; i < 4; i++){
        int g = g0 + ty*4 + i;
        float cg = cb[g];
        #pragma unroll
        for (int j = 0; j < 4; j++){
            int h = h0 + tx*4 + j;
            float pg  = g_P[g*H_ + h];
            float qg  = g_Q[g*H_ + h];
            float a2  = A2b[g*H_ + h];
            float a2t = A2b[h*H_ + g];
            local += cg*cb[h]*pg*(qg*acc[i][j] + a2*a2t);
        }
    }
    __shared__ float red[256];
    red[tid] = local;
    __syncthreads();
    for (int st = 128; st > 0; st >>= 1){
        if (tid < st) red[tid] += red[tid + st];
        __syncthreads();
    }
    if (tid == 0) g_part[b*16 + blockIdx.y*4 + blockIdx.x] = red[0];
}

// ==================== stage 4: finalize ====================
__global__ void k_final(const float* __restrict__ state, float* __restrict__ out){
    int b = blockIdx.x, tid = threadIdx.x;   // 128 threads
    __shared__ float nrm_s;
    if (tid == 0){
        float sum = 0.f;
        #pragma unroll
        for (int i = 0; i < 16; i++) sum += g_part[b*16 + i];
        nrm_s = sqrtf(fmaxf(2.f*sum, 0.f));
    }
    __syncthreads();
    float nrm = nrm_s;
    float vn  = g_vn[b];
    float v   = state[(B_+b)*N_ + tid];
    float dev = state[b*N_ + tid];
    float a = -(g_Avec[b*N_ + tid] - 0.5f*g_Cvec[b*N_ + tid])
              / ((nrm + 1e-6f) * (vn + 1e-6f));
    out[b*N_ + tid]       = v;
    out[(B_+b)*N_ + tid]  = a - 0.1f*dev;
}

// -------- launch --------
extern "C" void kernel_launch(void* const* d_in, const int* in_sizes, int n_in,
                              void* d_out, int out_size){
    const float* t     = (const float*)d_in[0];
    const float* state = (const float*)d_in[1];
    const float* x0    = (const float*)d_in[2];
    const float* x1    = (const float*)d_in[3];
    const float* W1    = (const float*)d_in[4];
    const float* b1    = (const float*)d_in[5];
    const float* W2    = (const float*)d_in[6];
    float* out = (float*)d_out;

    k_stage1<<<48,           256>>>(W1, W2, t, state, x0, x1, b1);
    k_A2    <<<dim3(4,4,B_), 256>>>();
    k_nrm   <<<dim3(4,4,B_), 256>>>();
    k_final <<<B_,           N_>>>(state, out);
}

// round 8
// speedup vs baseline: 1.9268x; 1.0232x over previous
#include <cuda_runtime.h>
#include <math.h>

#define N_ 128
#define H_ 256
#define B_ 16

// -------- device scratch --------
__device__ float g_P[H_*H_];        // W1^T W1
__device__ float g_Q[H_*H_];        // W2 W2^T
__device__ float g_s[B_*H_];
__device__ float g_c[B_*H_];
__device__ float g_Avec[B_*N_];
__device__ float g_Cvec[B_*N_];
__device__ float g_vn[B_];
__device__ float g_A2[B_*H_*H_];    // A2 = P S Q per sample
__device__ float g_part[B_*16];     // nrm^2/2 tile partials
__device__ unsigned int g_cnt[B_];  // last-block-done counters

#define FFMA2(d, a, b) \
    asm("fma.rn.f32x2 %0, %1, %2, %0;" : "+l"(d) : "l"(a), "l"(b))
#define DUP2(d, f) \
    asm("mov.b64 %0, {%1, %1};" : "=l"(d) : "f"(f))
#define UNPK2(lo, hi, d) \
    asm("mov.b64 {%0, %1}, %2;" : "=f"(lo), "=f"(hi) : "l"(d))

// packed 4x4 micro-step: ra = 4 floats, rbp = 2 packed f32x2 pairs
#define MICRO_STEP_F32X2(As_, Bs_)                                      \
    {   float4 ra = *(const float4*)&As_[k][ty*4];                      \
        ulonglong2 rbp = *(const ulonglong2*)&Bs_[k][tx*4];             \
        unsigned long long ad0, ad1, ad2, ad3;                          \
        DUP2(ad0, ra.x); DUP2(ad1, ra.y);                               \
        DUP2(ad2, ra.z); DUP2(ad3, ra.w);                               \
        FFMA2(accp[0][0], ad0, rbp.x); FFMA2(accp[0][1], ad0, rbp.y);   \
        FFMA2(accp[1][0], ad1, rbp.x); FFMA2(accp[1][1], ad1, rbp.y);   \
        FFMA2(accp[2][0], ad2, rbp.x); FFMA2(accp[2][1], ad2, rbp.y);   \
        FFMA2(accp[3][0], ad3, rbp.x); FFMA2(accp[3][1], ad3, rbp.y);   \
    }

#define UNPACK_ACC()                                                    \
    float acc[4][4];                                                    \
    _Pragma("unroll")                                                   \
    for (int i = 0; i < 4; i++){                                        \
        UNPK2(acc[i][0], acc[i][1], accp[i][0]);                        \
        UNPK2(acc[i][2], acc[i][3], accp[i][1]);                        \
    }

// ==================== stage 1: fused prep + vectors ====================
// blocks 0..15: P tiles, 16..31: Q tiles, 32..47: per-sample vectors.
__global__ void __launch_bounds__(256) k_stage1(
        const float* __restrict__ W1, const float* __restrict__ W2,
        const float* __restrict__ tptr, const float* __restrict__ state,
        const float* __restrict__ x0,  const float* __restrict__ x1,
        const float* __restrict__ b1){
    int bid = blockIdx.x;
    int tid = threadIdx.x;

    if (bid < 32){
        int z = bid >> 4, tile = bid & 15;
        int g0 = (tile >> 2)*64, h0 = (tile & 3)*64;
        __shared__ float As[16][68];
        __shared__ float Bs[16][68];
        int ty = tid >> 4, tx = tid & 15;
        unsigned long long accp[4][2] = {{0ull,0ull},{0ull,0ull},{0ull,0ull},{0ull,0ull}};

        for (int a0 = 0; a0 < N_; a0 += 16){
            if (z == 0){
                int a = tid >> 4, q4 = (tid & 15)*4;
                *(float4*)&As[a][q4] = *(const float4*)&W1[(a0+a)*H_ + g0 + q4];
                *(float4*)&Bs[a][q4] = *(const float4*)&W1[(a0+a)*H_ + h0 + q4];
            } else {
                int gg = tid >> 2, kq = (tid & 3)*4;
                float4 av = *(const float4*)&W2[(g0+gg)*N_ + a0 + kq];
                float4 bv = *(const float4*)&W2[(h0+gg)*N_ + a0 + kq];
                As[kq+0][gg] = av.x; As[kq+1][gg] = av.y;
                As[kq+2][gg] = av.z; As[kq+3][gg] = av.w;
                Bs[kq+0][gg] = bv.x; Bs[kq+1][gg] = bv.y;
                Bs[kq+2][gg] = bv.z; Bs[kq+3][gg] = bv.w;
            }
            __syncthreads();
            #pragma unroll
            for (int k = 0; k < 16; k++) MICRO_STEP_F32X2(As, Bs)
            __syncthreads();
        }
        UNPACK_ACC()
        float* dst = (z == 0) ? g_P : g_Q;
        #pragma unroll
        for (int i = 0; i < 4; i++){
            float4 o = make_float4(acc[i][0], acc[i][1], acc[i][2], acc[i][3]);
            *(float4*)&dst[(g0+ty*4+i)*H_ + h0 + tx*4] = o;
        }
        return;
    }

    // ---- per-sample vector pipeline (P x computed as W1^T(W1 x)) ----
    int b = bid - 32;
    __shared__ float xs[N_], vs[N_], red[N_];
    __shared__ float ws[H_], swv[H_], cwy[H_], pvs[H_], cwz[H_];
    __shared__ float r1[N_], r2[N_], Ap[2*N_];

    float tval = *tptr;
    float window = 4.f * tval * (1.f - tval);
    if (tid < N_){
        float dev = state[b*N_ + tid];
        float v   = state[(B_+b)*N_ + tid];
        float x0v = x0[b*N_ + tid];
        xs[tid] = x0v + tval*(x1[b*N_ + tid] - x0v) + window*dev;
        vs[tid] = v;
        red[tid] = v*v;
    }
    __syncthreads();

    if (tid < 32){
        float a0 = red[tid] + red[tid+32] + red[tid+64] + red[tid+96];
        #pragma unroll
        for (int o = 16; o; o >>= 1) a0 += __shfl_xor_sync(0xffffffffu, a0, o);
        if (tid == 0) g_vn[b] = sqrtf(a0);
    }

    int h = tid;
    int wid = tid >> 5, lane = tid & 31;

    float u = 0.f, y = 0.f;
    #pragma unroll 8
    for (int k = 0; k < N_; k++){
        float w1 = W1[k*H_ + h];
        u += xs[k]*w1;
        y += vs[k]*w1;
    }
    for (int r = 0; r < 32; r++){
        int row = wid*32 + r;
        const float* wr = W2 + row*N_;
        float sum = wr[lane]*vs[lane] + wr[lane+32]*vs[lane+32]
                  + wr[lane+64]*vs[lane+64] + wr[lane+96]*vs[lane+96];
        #pragma unroll
        for (int o = 16; o; o >>= 1) sum += __shfl_xor_sync(0xffffffffu, sum, o);
        if (lane == 0) ws[row] = sum;
    }
    __syncthreads();

    float th = tanhf(u + b1[h]);
    float s = 1.f - th*th;
    float c = -2.f*th*s;
    g_s[b*H_ + h] = s;
    g_c[b*H_ + h] = c;
    float wv = ws[h];
    swv[h] = s*wv;
    cwy[h] = c*wv*y;
    __syncthreads();

    for (int r = 0; r < 16; r++){
        int row = wid*16 + r;
        const float* wr = W1 + row*H_;
        float s1 = 0.f, s2 = 0.f;
        #pragma unroll
        for (int jj = 0; jj < 8; jj++){
            int hh = lane + jj*32;
            float w1 = wr[hh];
            s1 += w1*swv[hh];
            s2 += w1*cwy[hh];
        }
        #pragma unroll
        for (int o = 16; o; o >>= 1){
            s1 += __shfl_xor_sync(0xffffffffu, s1, o);
            s2 += __shfl_xor_sync(0xffffffffu, s2, o);
        }
        if (lane == 0){ r1[row] = s1; r2[row] = s2; }
    }
    __syncthreads();

    float z = 0.f, q2 = 0.f;
    #pragma unroll 8
    for (int k = 0; k < N_; k++){
        float w1 = W1[k*H_ + h];
        z  += w1*r1[k];
        q2 += w1*r2[k];
    }
    pvs[h] = c*y*z + s*q2;
    cwz[h] = c*wv*z;
    __syncthreads();

    {
        int i = tid & 127, q = tid >> 7;
        float A = 0.f;
        #pragma unroll 8
        for (int j = 0; j < 128; j++){
            int hh = q*128 + j;
            A += W2[hh*N_ + i]*pvs[hh];
        }
        Ap[tid] = A;
    }
    for (int r = 0; r < 16; r++){
        int row = wid*16 + r;
        const float* wr = W1 + row*H_;
        float sC = 0.f;
        #pragma unroll
        for (int jj = 0; jj < 8; jj++){
            int hh = lane + jj*32;
            sC += wr[hh]*cwz[hh];
        }
        #pragma unroll
        for (int o = 16; o; o >>= 1) sC += __shfl_xor_sync(0xffffffffu, sC, o);
        if (lane == 0) g_Cvec[b*N_ + row] = 2.f*sC;
    }
    __syncthreads();
    if (tid < N_) g_Avec[b*N_ + tid] = Ap[tid] + Ap[tid + N_];
}

// ==================== stage 2: A2[b] = P diag(s) Q ====================
__global__ void __launch_bounds__(256) k_A2(){
    int b  = blockIdx.z;
    int g0 = blockIdx.y*64, h0 = blockIdx.x*64;
    int tid = threadIdx.x;
    if (blockIdx.x == 0 && blockIdx.y == 0 && tid == 0) g_cnt[b] = 0;  // reset for k_nrm
    int ty = tid >> 4, tx = tid & 15;
    __shared__ float Ps[16][68];
    __shared__ float Qs[16][68];
    __shared__ float ssm[H_];
    ssm[tid] = g_s[b*H_ + tid];
    unsigned long long accp[4][2] = {{0ull,0ull},{0ull,0ull},{0ull,0ull},{0ull,0ull}};
    __syncthreads();

    int a = tid >> 4, q4 = (tid & 15)*4;
    for (int a0 = 0; a0 < H_; a0 += 16){
        float4 pv = *(const float4*)&g_P[(a0+a)*H_ + g0 + q4];   // P symmetric
        float4 qv = *(const float4*)&g_Q[(a0+a)*H_ + h0 + q4];
        float sa = ssm[a0+a];
        qv.x *= sa; qv.y *= sa; qv.z *= sa; qv.w *= sa;
        *(float4*)&Ps[a][q4] = pv;
        *(float4*)&Qs[a][q4] = qv;
        __syncthreads();
        #pragma unroll
        for (int k = 0; k < 16; k++) MICRO_STEP_F32X2(Ps, Qs)
        __syncthreads();
    }
    UNPACK_ACC()
    float* dst = g_A2 + b*H_*H_;
    #pragma unroll
    for (int i = 0; i < 4; i++){
        float4 o = make_float4(acc[i][0], acc[i][1], acc[i][2], acc[i][3]);
        *(float4*)&dst[(g0+ty*4+i)*H_ + h0 + tx*4] = o;
    }
}

// ========== stage 3: fused A1 = A2 diag(s) P + reduction + finalize ==========
__global__ void __launch_bounds__(256) k_nrm(const float* __restrict__ state,
                                             float* __restrict__ out){
    int b  = blockIdx.z;
    int g0 = blockIdx.y*64, h0 = blockIdx.x*64;
    int tid = threadIdx.x;
    int ty = tid >> 4, tx = tid & 15;
    __shared__ float As[16][68];
    __shared__ float Bs[16][68];
    __shared__ float ssm[H_];
    ssm[tid] = g_s[b*H_ + tid];
    unsigned long long accp[4][2] = {{0ull,0ull},{0ull,0ull},{0ull,0ull},{0ull,0ull}};
    __syncthreads();

    const float* A2b = g_A2 + b*H_*H_;
    int gg = tid >> 2, aq = (tid & 3)*4;
    int ab = tid >> 4, q4 = (tid & 15)*4;
    for (int a0 = 0; a0 < H_; a0 += 16){
        float4 av = *(const float4*)&A2b[(g0+gg)*H_ + a0 + aq];
        As[aq+0][gg] = av.x*ssm[a0+aq+0];
        As[aq+1][gg] = av.y*ssm[a0+aq+1];
        As[aq+2][gg] = av.z*ssm[a0+aq+2];
        As[aq+3][gg] = av.w*ssm[a0+aq+3];
        *(float4*)&Bs[ab][q4] = *(const float4*)&g_P[(a0+ab)*H_ + h0 + q4];
        __syncthreads();
        #pragma unroll
        for (int k = 0; k < 16; k++) MICRO_STEP_F32X2(As, Bs)
        __syncthreads();
    }
    UNPACK_ACC()

    const float* cb = g_c + b*H_;
    float local = 0.f;
    #pragma unroll
    for (int i = 0; i < 4; i++){
        int g = g0 + ty*4 + i;
        float cg = cb[g];
        #pragma unroll
        for (int j = 0; j < 4; j++){
            int h = h0 + tx*4 + j;
            float pg  = g_P[g*H_ + h];
            float qg  = g_Q[g*H_ + h];
            float a2  = A2b[g*H_ + h];
            float a2t = A2b[h*H_ + g];
            local += cg*cb[h]*pg*(qg*acc[i][j] + a2*a2t);
        }
    }
    __shared__ float red[256];
    red[tid] = local;
    __syncthreads();
    for (int st = 128; st > 0; st >>= 1){
        if (tid < st) red[tid] += red[tid + st];
        __syncthreads();
    }
    __shared__ unsigned int is_last;
    if (tid == 0){
        g_part[b*16 + blockIdx.y*4 + blockIdx.x] = red[0];
        __threadfence();
        is_last = (atomicAdd(&g_cnt[b], 1u) == 15u);
    }
    __syncthreads();

    if (is_last && tid < N_){
        // deterministic: all 16 partials for this b are visible (fence+atomic)
        float sum = 0.f;
        #pragma unroll
        for (int i = 0; i < 16; i++) sum += g_part[b*16 + i];
        float nrm = sqrtf(fmaxf(2.f*sum, 0.f));
        float vn  = g_vn[b];
        float v   = state[(B_+b)*N_ + tid];
        float dev = state[b*N_ + tid];
        float aout = -(g_Avec[b*N_ + tid] - 0.5f*g_Cvec[b*N_ + tid])
                     / ((nrm + 1e-6f) * (vn + 1e-6f));
        out[b*N_ + tid]       = v;
        out[(B_+b)*N_ + tid]  = aout - 0.1f*dev;
    }
}

// -------- launch --------
extern "C" void kernel_launch(void* const* d_in, const int* in_sizes, int n_in,
                              void* d_out, int out_size){
    const float* t     = (const float*)d_in[0];
    const float* state = (const float*)d_in[1];
    const float* x0    = (const float*)d_in[2];
    const float* x1    = (const float*)d_in[3];
    const float* W1    = (const float*)d_in[4];
    const float* b1    = (const float*)d_in[5];
    const float* W2    = (const float*)d_in[6];
    float* out = (float*)d_out;

    k_stage1<<<48,           256>>>(W1, W2, t, state, x0, x1, b1);
    k_A2    <<<dim3(4,4,B_), 256>>>();
    k_nrm   <<<dim3(4,4,B_), 256>>>(state, out);
}

// round 9
// speedup vs baseline: 1.9472x; 1.0106x over previous
#include <cuda_runtime.h>
#include <math.h>

#define N_ 128
#define H_ 256
#define B_ 16

// -------- device scratch --------
__device__ float g_P[H_*H_];        // W1^T W1
__device__ float g_Q[H_*H_];        // W2 W2^T
__device__ float g_W1T[H_*N_];      // W1T[h*N+i] = W1[i*H+h]
__device__ float g_W2T[N_*H_];      // W2T[k*H+h] = W2[h*N+k]
__device__ float g_s[B_*H_];
__device__ float g_c[B_*H_];
__device__ float g_Avec[B_*N_];
__device__ float g_Cvec[B_*N_];
__device__ float g_vn[B_];
__device__ float g_A2[B_*H_*H_];    // A2 = P S Q per sample
__device__ float g_part[B_*16];     // nrm^2/2 tile partials
__device__ unsigned int g_cnt[B_];  // last-block-done counters

#define FFMA2(d, a, b) \
    asm("fma.rn.f32x2 %0, %1, %2, %0;" : "+l"(d) : "l"(a), "l"(b))
#define DUP2(d, f) \
    asm("mov.b64 %0, {%1, %1};" : "=l"(d) : "f"(f))
#define UNPK2(lo, hi, d) \
    asm("mov.b64 {%0, %1}, %2;" : "=f"(lo), "=f"(hi) : "l"(d))

#define MICRO_STEP_F32X2(As_, Bs_)                                      \
    {   float4 ra = *(const float4*)&As_[k][ty*4];                      \
        ulonglong2 rbp = *(const ulonglong2*)&Bs_[k][tx*4];             \
        unsigned long long ad0, ad1, ad2, ad3;                          \
        DUP2(ad0, ra.x); DUP2(ad1, ra.y);                               \
        DUP2(ad2, ra.z); DUP2(ad3, ra.w);                               \
        FFMA2(accp[0][0], ad0, rbp.x); FFMA2(accp[0][1], ad0, rbp.y);   \
        FFMA2(accp[1][0], ad1, rbp.x); FFMA2(accp[1][1], ad1, rbp.y);   \
        FFMA2(accp[2][0], ad2, rbp.x); FFMA2(accp[2][1], ad2, rbp.y);   \
        FFMA2(accp[3][0], ad3, rbp.x); FFMA2(accp[3][1], ad3, rbp.y);   \
    }

#define UNPACK_ACC()                                                    \
    float acc[4][4];                                                    \
    _Pragma("unroll")                                                   \
    for (int i = 0; i < 4; i++){                                        \
        UNPK2(acc[i][0], acc[i][1], accp[i][0]);                        \
        UNPK2(acc[i][2], acc[i][3], accp[i][1]);                        \
    }

// ==================== kernel 0: transposes ====================
// blocks 0..31: W1 [128x256] -> W1T [256x128]; 32..63: W2 [256x128] -> W2T [128x256]
__global__ void __launch_bounds__(256) k_tr(const float* __restrict__ W1,
                                            const float* __restrict__ W2){
    __shared__ float ts[32][33];
    int bid = blockIdx.x;
    int tid = threadIdx.x;
    int r0 = tid >> 5, cc = tid & 31;
    if (bid < 32){
        int ti = bid >> 3, th = bid & 7;       // 4 x 8 tiles
        #pragma unroll
        for (int r = r0; r < 32; r += 8)
            ts[r][cc] = W1[(ti*32 + r)*H_ + th*32 + cc];
        __syncthreads();
        #pragma unroll
        for (int r = r0; r < 32; r += 8)
            g_W1T[(th*32 + r)*N_ + ti*32 + cc] = ts[cc][r];
    } else {
        int b2 = bid - 32;
        int th = b2 >> 2, tk = b2 & 3;         // 8 x 4 tiles
        #pragma unroll
        for (int r = r0; r < 32; r += 8)
            ts[r][cc] = W2[(th*32 + r)*N_ + tk*32 + cc];
        __syncthreads();
        #pragma unroll
        for (int r = r0; r < 32; r += 8)
            g_W2T[(tk*32 + r)*H_ + th*32 + cc] = ts[cc][r];
    }
}

// ==================== stage 1: fused P/Q GEMM + vectors ====================
// blocks 0..15: P tiles, 16..31: Q tiles, 32..47: per-sample vectors.
__global__ void __launch_bounds__(256) k_stage1(
        const float* __restrict__ W1, const float* __restrict__ W2,
        const float* __restrict__ tptr, const float* __restrict__ state,
        const float* __restrict__ x0,  const float* __restrict__ x1,
        const float* __restrict__ b1){
    int bid = blockIdx.x;
    int tid = threadIdx.x;

    if (bid < 32){
        int z = bid >> 4, tile = bid & 15;
        int g0 = (tile >> 2)*64, h0 = (tile & 3)*64;
        __shared__ float As[16][68];
        __shared__ float Bs[16][68];
        int ty = tid >> 4, tx = tid & 15;
        unsigned long long accp[4][2] = {{0ull,0ull},{0ull,0ull},{0ull,0ull},{0ull,0ull}};

        for (int a0 = 0; a0 < N_; a0 += 16){
            if (z == 0){
                int a = tid >> 4, q4 = (tid & 15)*4;
                *(float4*)&As[a][q4] = *(const float4*)&W1[(a0+a)*H_ + g0 + q4];
                *(float4*)&Bs[a][q4] = *(const float4*)&W1[(a0+a)*H_ + h0 + q4];
            } else {
                int gg = tid >> 2, kq = (tid & 3)*4;
                float4 av = *(const float4*)&W2[(g0+gg)*N_ + a0 + kq];
                float4 bv = *(const float4*)&W2[(h0+gg)*N_ + a0 + kq];
                As[kq+0][gg] = av.x; As[kq+1][gg] = av.y;
                As[kq+2][gg] = av.z; As[kq+3][gg] = av.w;
                Bs[kq+0][gg] = bv.x; Bs[kq+1][gg] = bv.y;
                Bs[kq+2][gg] = bv.z; Bs[kq+3][gg] = bv.w;
            }
            __syncthreads();
            #pragma unroll
            for (int k = 0; k < 16; k++) MICRO_STEP_F32X2(As, Bs)
            __syncthreads();
        }
        UNPACK_ACC()
        float* dst = (z == 0) ? g_P : g_Q;
        #pragma unroll
        for (int i = 0; i < 4; i++){
            float4 o = make_float4(acc[i][0], acc[i][1], acc[i][2], acc[i][3]);
            *(float4*)&dst[(g0+ty*4+i)*H_ + h0 + tx*4] = o;
        }
        return;
    }

    // ---- per-sample vector pipeline: all phases coalesced, no shfl GEMV ----
    int b = bid - 32;
    __shared__ float xs[N_], vs[N_], red[N_];
    __shared__ float swv[H_], cwy[H_], pvs[H_], cwz[H_];
    __shared__ float r1p[2][N_], r2p[2][N_], r1s[N_], r2s[N_];
    __shared__ float Ap[2][N_], Cp[2][N_];

    float tval = *tptr;
    float window = 4.f * tval * (1.f - tval);
    if (tid < N_){
        float dev = state[b*N_ + tid];
        float v   = state[(B_+b)*N_ + tid];
        float x0v = x0[b*N_ + tid];
        xs[tid] = x0v + tval*(x1[b*N_ + tid] - x0v) + window*dev;
        vs[tid] = v;
        red[tid] = v*v;
    }
    __syncthreads();

    if (tid < 32){
        float a0 = red[tid] + red[tid+32] + red[tid+64] + red[tid+96];
        #pragma unroll
        for (int o = 16; o; o >>= 1) a0 += __shfl_xor_sync(0xffffffffu, a0, o);
        if (tid == 0) g_vn[b] = sqrtf(a0);
    }

    int h = tid;
    // phase B: u, y (W1 cols), w (W2T cols) -- coalesced across h
    float u = 0.f, y = 0.f, w = 0.f;
    #pragma unroll 8
    for (int k = 0; k < N_; k++){
        float w1 = W1[k*H_ + h];
        u += xs[k]*w1;
        y += vs[k]*w1;
        w += g_W2T[k*H_ + h]*vs[k];
    }
    float th = tanhf(u + b1[h]);
    float s = 1.f - th*th;
    float c = -2.f*th*s;
    g_s[b*H_ + h] = s;
    g_c[b*H_ + h] = c;
    swv[h] = s*w;
    cwy[h] = c*w*y;
    __syncthreads();

    // phase C: r1 = W1*swv, r2 = W1*cwy via W1T (2 threads per output k)
    {
        int kk = tid & 127, half = tid >> 7;
        float s1 = 0.f, s2 = 0.f;
        #pragma unroll 8
        for (int j = 0; j < 128; j++){
            int hh = half*128 + j;
            float w1t = g_W1T[hh*N_ + kk];
            s1 += w1t*swv[hh];
            s2 += w1t*cwy[hh];
        }
        r1p[half][kk] = s1;
        r2p[half][kk] = s2;
    }
    __syncthreads();
    if (tid < N_){
        r1s[tid] = r1p[0][tid] + r1p[1][tid];
        r2s[tid] = r2p[0][tid] + r2p[1][tid];
    }
    __syncthreads();

    // phase D: z = W1^T r1, q2 = W1^T r2 -- coalesced across h
    float z = 0.f, q2 = 0.f;
    #pragma unroll 8
    for (int k = 0; k < N_; k++){
        float w1 = W1[k*H_ + h];
        z  += w1*r1s[k];
        q2 += w1*r2s[k];
    }
    pvs[h] = c*y*z + s*q2;
    cwz[h] = c*w*z;
    __syncthreads();

    // phase E: A = W2^T pv (via W2), C = W1 cwz (via W1T) -- 2 threads per output i
    {
        int i = tid & 127, hf = tid >> 7;
        float A = 0.f, Cc = 0.f;
        #pragma unroll 8
        for (int j = 0; j < 128; j++){
            int hh = hf*128 + j;
            A  += W2[hh*N_ + i]*pvs[hh];
            Cc += g_W1T[hh*N_ + i]*cwz[hh];
        }
        Ap[hf][i] = A;
        Cp[hf][i] = Cc;
    }
    __syncthreads();
    if (tid < N_){
        g_Avec[b*N_ + tid] = Ap[0][tid] + Ap[1][tid];
        g_Cvec[b*N_ + tid] = 2.f*(Cp[0][tid] + Cp[1][tid]);
    }
}

// ==================== stage 2: A2[b] = P diag(s) Q ====================
__global__ void __launch_bounds__(256) k_A2(){
    int b  = blockIdx.z;
    int g0 = blockIdx.y*64, h0 = blockIdx.x*64;
    int tid = threadIdx.x;
    if (blockIdx.x == 0 && blockIdx.y == 0 && tid == 0) g_cnt[b] = 0;  // reset for k_nrm
    int ty = tid >> 4, tx = tid & 15;
    __shared__ float Ps[16][68];
    __shared__ float Qs[16][68];
    __shared__ float ssm[H_];
    ssm[tid] = g_s[b*H_ + tid];
    unsigned long long accp[4][2] = {{0ull,0ull},{0ull,0ull},{0ull,0ull},{0ull,0ull}};
    __syncthreads();

    int a = tid >> 4, q4 = (tid & 15)*4;
    for (int a0 = 0; a0 < H_; a0 += 16){
        float4 pv = *(const float4*)&g_P[(a0+a)*H_ + g0 + q4];   // P symmetric
        float4 qv = *(const float4*)&g_Q[(a0+a)*H_ + h0 + q4];
        float sa = ssm[a0+a];
        qv.x *= sa; qv.y *= sa; qv.z *= sa; qv.w *= sa;
        *(float4*)&Ps[a][q4] = pv;
        *(float4*)&Qs[a][q4] = qv;
        __syncthreads();
        #pragma unroll
        for (int k = 0; k < 16; k++) MICRO_STEP_F32X2(Ps, Qs)
        __syncthreads();
    }
    UNPACK_ACC()
    float* dst = g_A2 + b*H_*H_;
    #pragma unroll
    for (int i = 0; i < 4; i++){
        float4 o = make_float4(acc[i][0], acc[i][1], acc[i][2], acc[i][3]);
        *(float4*)&dst[(g0+ty*4+i)*H_ + h0 + tx*4] = o;
    }
}

// ========== stage 3: fused A1 = A2 diag(s) P + reduction + finalize ==========
__global__ void __launch_bounds__(256) k_nrm(const float* __restrict__ state,
                                             float* __restrict__ out){
    int b  = blockIdx.z;
    int g0 = blockIdx.y*64, h0 = blockIdx.x*64;
    int tid = threadIdx.x;
    int ty = tid >> 4, tx = tid & 15;
    __shared__ float As[16][68];
    __shared__ float Bs[16][68];
    __shared__ float ssm[H_];
    ssm[tid] = g_s[b*H_ + tid];
    unsigned long long accp[4][2] = {{0ull,0ull},{0ull,0ull},{0ull,0ull},{0ull,0ull}};
    __syncthreads();

    const float* A2b = g_A2 + b*H_*H_;
    int gg = tid >> 2, aq = (tid & 3)*4;
    int ab = tid >> 4, q4 = (tid & 15)*4;
    for (int a0 = 0; a0 < H_; a0 += 16){
        float4 av = *(const float4*)&A2b[(g0+gg)*H_ + a0 + aq];
        As[aq+0][gg] = av.x*ssm[a0+aq+0];
        As[aq+1][gg] = av.y*ssm[a0+aq+1];
        As[aq+2][gg] = av.z*ssm[a0+aq+2];
        As[aq+3][gg] = av.w*ssm[a0+aq+3];
        *(float4*)&Bs[ab][q4] = *(const float4*)&g_P[(a0+ab)*H_ + h0 + q4];
        __syncthreads();
        #pragma unroll
        for (int k = 0; k < 16; k++) MICRO_STEP_F32X2(As, Bs)
        __syncthreads();
    }
    UNPACK_ACC()

    const float* cb = g_c + b*H_;
    float local = 0.f;
    #pragma unroll
    for (int i = 0; i < 4; i++){
        int g = g0 + ty*4 + i;
        float cg = cb[g];
        #pragma unroll
        for (int j = 0; j < 4; j++){
            int h = h0 + tx*4 + j;
            float pg  = g_P[g*H_ + h];
            float qg  = g_Q[g*H_ + h];
            float a2  = A2b[g*H_ + h];
            float a2t = A2b[h*H_ + g];
            local += cg*cb[h]*pg*(qg*acc[i][j] + a2*a2t);
        }
    }
    __shared__ float red[256];
    red[tid] = local;
    __syncthreads();
    for (int st = 128; st > 0; st >>= 1){
        if (tid < st) red[tid] += red[tid + st];
        __syncthreads();
    }
    __shared__ unsigned int is_last;
    if (tid == 0){
        g_part[b*16 + blockIdx.y*4 + blockIdx.x] = red[0];
        __threadfence();
        is_last = (atomicAdd(&g_cnt[b], 1u) == 15u);
    }
    __syncthreads();

    if (is_last && tid < N_){
        float sum = 0.f;
        #pragma unroll
        for (int i = 0; i < 16; i++) sum += g_part[b*16 + i];
        float nrm = sqrtf(fmaxf(2.f*sum, 0.f));
        float vn  = g_vn[b];
        float v   = state[(B_+b)*N_ + tid];
        float dev = state[b*N_ + tid];
        float aout = -(g_Avec[b*N_ + tid] - 0.5f*g_Cvec[b*N_ + tid])
                     / ((nrm + 1e-6f) * (vn + 1e-6f));
        out[b*N_ + tid]       = v;
        out[(B_+b)*N_ + tid]  = aout - 0.1f*dev;
    }
}

// -------- launch --------
extern "C" void kernel_launch(void* const* d_in, const int* in_sizes, int n_in,
                              void* d_out, int out_size){
    const float* t     = (const float*)d_in[0];
    const float* state = (const float*)d_in[1];
    const float* x0    = (const float*)d_in[2];
    const float* x1    = (const float*)d_in[3];
    const float* W1    = (const float*)d_in[4];
    const float* b1    = (const float*)d_in[5];
    const float* W2    = (const float*)d_in[6];
    float* out = (float*)d_out;

    k_tr    <<<64,           256>>>(W1, W2);
    k_stage1<<<48,           256>>>(W1, W2, t, state, x0, x1, b1);
    k_A2    <<<dim3(4,4,B_), 256>>>();
    k_nrm   <<<dim3(4,4,B_), 256>>>(state, out);
}